// round 15
// baseline (speedup 1.0000x reference)
#include <cuda_runtime.h>
#include <math.h>
#include <stdint.h>

#define HH 360
#define WW 640
#define NP (HH*WW)          // 230400
#define NPLANES 1000
#define NPAIR   500
#define MINPTS 5000

#define CXc 334.081f
#define CYc 169.808f
#define FXc 460.585f
#define FYc 460.268f

#define NB 148
#define NT 960
#define NWARP 30
#define PX 10               // pixels per slot (divides 640)
#define SLOTS 160           // pixel slots per block
#define NACT 23040          // active slots total (NACT*PX = NP)
#define NGRP 6              // plane groups (5 warps each)
#define GRPW 5
#define GSZ 84              // pairs per group (last group: 500-5*84=80)
#define NF2 115200          // float2s per image
#define CHUNK2 779          // float2s per block in phase A

// ---------------- scratch ----------------
__device__ float    g_partA[NB * 6];     // cnt, dx2, dy2, dz2, dlog2, max
__device__ float    g_pp[8 * NPAIR];     // interleaved pair planes (scaled w)
__device__ int      g_counts[NPLANES];
__device__ float    g_partB[NB * 4];     // ic, zmax, zmin, sumzc
__device__ unsigned g_arrive;
__device__ volatile unsigned g_gen;

// ---------------- helpers ----------------
__host__ __device__ __forceinline__ uint32_t rotl32(uint32_t v, int s) { return (v << s) | (v >> (32 - s)); }

__host__ __device__ __forceinline__ void threefry2x32(uint32_t k0, uint32_t k1, uint32_t x0, uint32_t x1,
                                                      uint32_t& o0, uint32_t& o1) {
    uint32_t ks2 = k0 ^ k1 ^ 0x1BD11BDAu;
    x0 += k0; x1 += k1;
#define TFR(R) { x0 += x1; x1 = rotl32(x1, R); x1 ^= x0; }
    TFR(13) TFR(15) TFR(26) TFR(6)
    x0 += k1;  x1 += ks2 + 1u;
    TFR(17) TFR(29) TFR(16) TFR(24)
    x0 += ks2; x1 += k0 + 2u;
    TFR(13) TFR(15) TFR(26) TFR(6)
    x0 += k0;  x1 += k1 + 3u;
    TFR(17) TFR(29) TFR(16) TFR(24)
    x0 += k1;  x1 += ks2 + 4u;
    TFR(13) TFR(15) TFR(26) TFR(6)
    x0 += ks2; x1 += k0 + 5u;
#undef TFR
    o0 = x0; o1 = x1;
}

// packed f32x2
__device__ __forceinline__ unsigned long long pk2(float lo, float hi) {
    unsigned long long r;
    asm("mov.b64 %0, {%1, %2};" : "=l"(r) : "f"(lo), "f"(hi));
    return r;
}
__device__ __forceinline__ void upk2(unsigned long long v, float& lo, float& hi) {
    asm("mov.b64 {%0, %1}, %2;" : "=f"(lo), "=f"(hi) : "l"(v));
}
__device__ __forceinline__ unsigned long long ffma2(unsigned long long a, unsigned long long b, unsigned long long c) {
    unsigned long long r;
    asm("fma.rn.f32x2 %0, %1, %2, %3;" : "=l"(r) : "l"(a), "l"(b), "l"(c));
    return r;
}
// |x| <= th ? +1.0 : +0.0 accumulated (FSET + FADD, fma pipe, no predicates). NaN -> +0.
__device__ __forceinline__ void fcount(float& acc, float x, float th) {
    asm("{ .reg .f32 ta, ts;\n\t"
        "  abs.f32 ta, %1;\n\t"
        "  set.le.f32.f32 ts, ta, %2;\n\t"
        "  add.f32 %0, %0, ts; }"
        : "+f"(acc) : "f"(x), "f"(th));
}

// UNNORMALIZED point (fake_pcd*1000, eps-filtered, nan->0)
__device__ __forceinline__ void pts_unnorm(const float* __restrict__ fake, int p,
                                           float& x, float& y, float& z) {
    float d = fake[p];
    bool valid = (d > 0.0f) && (d < 65535.0f);
    int r = p / WW, c = p - r * WW;
    float zz = d / 1000.0f;
    float px = zz * ((float)c - CXc) / FXc * 1000.0f;
    float py = zz * ((float)r - CYc) / FYc * 1000.0f;
    float pz = zz * 1000.0f;
    if (px == 0.0f) px = 1e-7f;
    if (py == 0.0f) py = 1e-7f;
    if (pz == 0.0f) pz = 1e-7f;
    if (!valid) { px = 0.0f; py = 0.0f; pz = 0.0f; }
    x = px; y = py; z = pz;
}

// ---------------- software grid barrier ----------------
__device__ __forceinline__ void gbar() {
    __syncthreads();
    __threadfence();
    if (threadIdx.x == 0) {
        unsigned g = g_gen;
        if (atomicAdd(&g_arrive, 1u) == NB - 1u) {
            atomicExch(&g_arrive, 0u);
            __threadfence();
            g_gen = g + 1u;
        } else {
            while (g_gen == g) { __nanosleep(64); }
        }
        __threadfence();
    }
    __syncthreads();
}

// warp-local reduce helpers (no sync)
__device__ __forceinline__ float wsum(float v) {
    for (int o = 16; o; o >>= 1) v += __shfl_down_sync(0xffffffffu, v, o);
    return v;
}
__device__ __forceinline__ float wmax(float v) {
    for (int o = 16; o; o >>= 1) v = fmaxf(v, __shfl_down_sync(0xffffffffu, v, o));
    return v;
}
__device__ __forceinline__ float wmin(float v) {
    for (int o = 16; o; o >>= 1) v = fminf(v, __shfl_down_sync(0xffffffffu, v, o));
    return v;
}

// classic block reductions (for once-per-kernel paths)
__device__ __forceinline__ float blk_sum(float v, float* s30) {
    __syncthreads();
    int lane = threadIdx.x & 31, w = threadIdx.x >> 5;
    v = wsum(v);
    if (lane == 0) s30[w] = v;
    __syncthreads();
    float r = 0.0f;
    if (threadIdx.x == 0) { for (int i = 0; i < NWARP; i++) r += s30[i]; }
    return r;
}
__device__ __forceinline__ float blk_max(float v, float* s30) {
    __syncthreads();
    int lane = threadIdx.x & 31, w = threadIdx.x >> 5;
    v = wmax(v);
    if (lane == 0) s30[w] = v;
    __syncthreads();
    float r = -INFINITY;
    if (threadIdx.x == 0) { for (int i = 0; i < NWARP; i++) r = fmaxf(r, s30[i]); }
    return r;
}
__device__ __forceinline__ float blk_min(float v, float* s30) {
    __syncthreads();
    int lane = threadIdx.x & 31, w = threadIdx.x >> 5;
    v = wmin(v);
    if (lane == 0) s30[w] = v;
    __syncthreads();
    float r = INFINITY;
    if (threadIdx.x == 0) { for (int i = 0; i < NWARP; i++) r = fminf(r, s30[i]); }
    return r;
}
__device__ __forceinline__ long long blk_maxll(long long v, long long* s30) {
    __syncthreads();
    int lane = threadIdx.x & 31, w = threadIdx.x >> 5;
    for (int o = 16; o; o >>= 1) {
        long long t = __shfl_down_sync(0xffffffffu, v, o);
        if (t > v) v = t;
    }
    if (lane == 0) s30[w] = v;
    __syncthreads();
    long long r = (-1LL) << 62;
    if (threadIdx.x == 0) { for (int i = 0; i < NWARP; i++) if (s30[i] > r) r = s30[i]; }
    return r;
}

// ---------------- the one kernel ----------------
__global__ void __launch_bounds__(NT) k_all(const float* __restrict__ fake,
                                            const float* __restrict__ real,
                                            const int* __restrict__ epoch_ptr,
                                            float* __restrict__ out,
                                            uint32_t ka, uint32_t kb) {
    __shared__ float     spp[8 * NPAIR];          // 16000 B
    __shared__ unsigned  swarp[NWARP * GSZ];      // 10080 B
    __shared__ float     s30[NWARP];
    __shared__ long long sll[NWARP];
    __shared__ float     s6[NWARP][6];
    __shared__ float     s4[NWARP][4];
    __shared__ float     sbc[16];
    __shared__ unsigned  sh_last;

    const int tid = threadIdx.x;
    const int b = blockIdx.x;
    const int lane = tid & 31, wid = tid >> 5;

    // ================= Phase A =================
    if (tid >= 32 && tid < 39) {
        int i = b * 7 + (tid - 32);
        if (i < NPLANES) g_counts[i] = 0;
    }

    // --- count point setup (UNNORMALIZED Z) ---
    const int slot = tid % SLOTS;
    const int grp = tid / SLOTS;
    const int gslot = b * SLOTS + slot;
    const bool act = gslot < NACT;
    const int p0 = act ? gslot * PX : 0;
    const int rowi = p0 / WW;
    const float vrow = ((float)rowi - CYc) / FYc;
    unsigned long long V = pk2(vrow, vrow);
    unsigned long long Up[PX], Zp[PX];
    {
        const float NaN = __int_as_float(0x7fffffff);
        int col0 = p0 - rowi * WW;
#pragma unroll
        for (int i = 0; i < PX; i++) {
            float d = __ldg(&fake[p0 + i]);
            bool val = (d > 0.0f) && (d < 65535.0f);
            float z = d / 1000.0f;
            float pz = z * 1000.0f;
            float Zi = val ? pz : 0.0f;
            if (!act) Zi = NaN;
            float ui = ((float)(col0 + i) - CXc) / FXc;
            Up[i] = pk2(ui, ui);
            Zp[i] = pk2(Zi, Zi);
        }
    }

    // --- plane generation ---
    if (tid < 7) {
        int pl = b * 7 + tid;
        if (pl < NPLANES) {
            float P[3][3];
#pragma unroll
            for (int j = 0; j < 3; j++) {
                uint32_t o0, o1;
                threefry2x32(ka, kb, 0u, (uint32_t)(pl * 3 + j), o0, o1);
                uint32_t idx = (o0 ^ o1) % (uint32_t)NP;
                pts_unnorm(fake, (int)idx, P[j][0], P[j][1], P[j][2]);
            }
            float ax = P[1][0] - P[0][0], ay = P[1][1] - P[0][1], az = P[1][2] - P[0][2];
            float bx = P[2][0] - P[0][0], by = P[2][1] - P[0][1], bz = P[2][2] - P[0][2];
            float nx = ay * bz - az * by;
            float ny = az * bx - ax * bz;
            float nz = ax * by - ay * bx;
            float nn = sqrtf(nx * nx + ny * ny + nz * nz);
            nx /= nn; ny /= nn; nz /= nn;
            float ws = -(nx * P[1][0] + ny * P[1][1] + nz * P[1][2]);
            int pr = pl >> 1, s = pl & 1;
            g_pp[8 * pr + 0 + s] = nx;
            g_pp[8 * pr + 2 + s] = ny;
            g_pp[8 * pr + 4 + s] = nz;
            g_pp[8 * pr + 6 + s] = ws;
        }
    }

    // --- pixel metrics (fused single-sync reduction) ---
    {
        float acnt = 0, adx = 0, ady = 0, adz = 0, adl = 0, amx = -INFINITY;
        int i = b * CHUNK2 + tid;
        if (tid < CHUNK2 && i < NF2) {
            float2 f2 = ((const float2*)fake)[i];
            float2 r2 = ((const float2*)real)[i];
#pragma unroll
            for (int j = 0; j < 2; j++) {
                int p = 2 * i + j;
                float fd = (&f2.x)[j], rd = (&r2.x)[j];
                int r = p / WW, c = p - r * WW;
                float cc = (float)c, rr = (float)r;
                bool vr = (rd > 0.0f) && (rd < 65535.0f);
                bool vf = (fd > 0.0f) && (fd < 65535.0f);

                float rz = rd / 1000.0f;
                float rX = rz * (cc - CXc) / FXc * 1000.0f;
                float rY = rz * (rr - CYc) / FYc * 1000.0f;
                float rZ = rz * 1000.0f;
                if (rX == 0.0f) rX = 1e-7f;
                if (rY == 0.0f) rY = 1e-7f;
                if (rZ == 0.0f) rZ = 1e-7f;

                float fz = fd / 1000.0f;
                float fX = fz * (cc - CXc) / FXc * 1000.0f;
                float fY = fz * (rr - CYc) / FYc * 1000.0f;
                float fZ = fz * 1000.0f;
                if (fX == 0.0f) fX = 1e-7f;
                if (fY == 0.0f) fY = 1e-7f;
                if (fZ == 0.0f) fZ = 1e-7f;

                bool m = vr && vf;
                if (m) {
                    float dx = rX - fX, dy = rY - fY, dz = rZ - fZ;
                    float dl = __logf(fabsf(rZ)) - __logf(fabsf(fZ));
                    acnt += 1.0f;
                    adx += dx * dx; ady += dy * dy; adz += dz * dz; adl += dl * dl;
                }
                if (vf) amx = fmaxf(amx, fmaxf(fmaxf(fX, fY), fZ));
            }
        }
        acnt = wsum(acnt); adx = wsum(adx); ady = wsum(ady);
        adz = wsum(adz); adl = wsum(adl); amx = wmax(amx);
        if (lane == 0) {
            s6[wid][0] = acnt; s6[wid][1] = adx; s6[wid][2] = ady;
            s6[wid][3] = adz; s6[wid][4] = adl; s6[wid][5] = amx;
        }
        __syncthreads();
        if (tid == 0) {
            float t0 = 0, t1 = 0, t2 = 0, t3 = 0, t4 = 0, t5 = -INFINITY;
            for (int w = 0; w < NWARP; w++) {
                t0 += s6[w][0]; t1 += s6[w][1]; t2 += s6[w][2];
                t3 += s6[w][3]; t4 += s6[w][4]; t5 = fmaxf(t5, s6[w][5]);
            }
            float* pa = &g_partA[b * 6];
            pa[0] = t0; pa[1] = t1; pa[2] = t2; pa[3] = t3; pa[4] = t4; pa[5] = t5;
        }
    }
    gbar();   // ===== B1 =====

    // --- per-block: maxv, th_s, rinv ---
    {
        float mx = -INFINITY;
        if (tid < NB) mx = g_partA[tid * 6 + 5];
        mx = blk_max(mx, s30);
        if (tid == 0) {
            int ep = epoch_ptr[0];
            float th = fmaxf((float)(0.025 - 0.001 * (double)ep), 0.005f);
            sbc[0] = mx;
            sbc[1] = th * mx;      // scaled threshold
            sbc[2] = 1.0f / mx;
        }
        __syncthreads();
    }
    const float th_s = sbc[1];

    // ================= Phase C: count =================
    {
        for (int i = tid; i < 2 * NPAIR; i += NT)
            ((float4*)spp)[i] = ((const float4*)g_pp)[i];
        __syncthreads();

        const int prBeg = grp * GSZ;
        const int prEnd = (grp == NGRP - 1) ? NPAIR : prBeg + GSZ;
        unsigned* myrow = swarp + wid * GSZ - prBeg;
        const float4* spp4 = (const float4*)spp;
#pragma unroll 2
        for (int pr = prBeg; pr < prEnd; pr++) {
            float4 q0 = spp4[2 * pr];      // a.lo a.hi b.lo b.hi
            float4 q1 = spp4[2 * pr + 1];  // c.lo c.hi w.lo w.hi (w scaled)
            unsigned long long A  = pk2(q0.x, q0.y);
            unsigned long long Bp = pk2(q0.z, q0.w);
            unsigned long long Cp = pk2(q1.x, q1.y);
            unsigned long long Wp = pk2(q1.z, q1.w);
            unsigned long long K = ffma2(V, Bp, Cp);
            float fclo = 0.0f, fchi = 0.0f;
#pragma unroll
            for (int i = 0; i < PX; i++) {
                unsigned long long e = ffma2(Up[i], A, K);
                unsigned long long dd = ffma2(Zp[i], e, Wp);
                float lo, hi;
                upk2(dd, lo, hi);
                fcount(fclo, lo, th_s);
                fcount(fchi, hi, th_s);
            }
            float cpkf = fmaf(fchi, 65536.0f, fclo);   // exact, < 2^24
            unsigned cpk = (unsigned)(int)cpkf;
            unsigned cs = __reduce_add_sync(0xffffffffu, cpk);
            if (lane == 0) myrow[pr] = cs;
        }
        __syncthreads();
        if (tid < NPAIR) {
            int pr = tid;
            int g = pr / GSZ;                  // 0..5
            int loc = pr - g * GSZ;
            unsigned s = 0;
#pragma unroll
            for (int w = 0; w < GRPW; w++) s += swarp[(g * GRPW + w) * GSZ + loc];
            atomicAdd(&g_counts[2 * pr],     (int)(s & 0xffffu));
            atomicAdd(&g_counts[2 * pr + 1], (int)(s >> 16));
        }
    }
    gbar();   // ===== B2 =====

    // ================= Phase D: argmax + zpass =================
    {
        long long bk = (-1LL) << 62;
        for (int t = tid; t < NPLANES; t += NT) {
            int cnt = g_counts[t];
            long long s = (cnt > MINPTS) ? (long long)cnt : -1LL;
            long long key = (s << 20) | (long long)(1023 - t);
            if (key > bk) bk = key;
        }
        bk = blk_maxll(bk, sll);
        if (tid == 0) {
            int best = 1023 - (int)(bk & 0xFFFFF);
            int pr = best >> 1, s = best & 1;
            float a  = spp[8 * pr + 0 + s];
            float bb = spp[8 * pr + 2 + s];
            float c  = spp[8 * pr + 4 + s];
            float ws = spp[8 * pr + 6 + s];
            float d = ws / sbc[0];            // normalized plane offset
            float tz = d / c;
            float n2 = a * a + bb * bb + c * c;
            float cos_t = c / sqrtf(n2);
            float sin_t = sqrtf((a * a + bb * bb) / n2);
            float sab = sqrtf(a * a + bb * bb);
            float u1 = bb / sab;
            float u2 = -a / sab;
            sbc[8]  = a; sbc[9] = bb; sbc[10] = c; sbc[11] = ws;
            sbc[12] = tz;
            sbc[13] = -u2 * sin_t;  // R[2][0]
            sbc[14] =  u1 * sin_t;  // R[2][1]
            sbc[15] =  cos_t;       // R[2][2]
        }
        __syncthreads();
        float a = sbc[8], bb = sbc[9], c = sbc[10], ws = sbc[11];
        float tz = sbc[12], r0 = sbc[13], r1 = sbc[14], r2 = sbc[15];
        float rinv = sbc[2];

        float aic = 0.0f, zmx = -INFINITY, zmn = INFINITY, szc = 0.0f;
        if (grp == 0) {
#pragma unroll
            for (int i = 0; i < PX; i++) {
                float u, Zu, dum;
                upk2(Up[i], u, dum);
                upk2(Zp[i], Zu, dum);
                float K = fmaf(vrow, bb, c);
                float e = fmaf(u, a, K);
                float dist = fmaf(Zu, e, ws);       // scaled dist
                bool inl = fabsf(dist) <= th_s;     // NaN -> false
                float Z = Zu * rinv;
                float x = Z * u, y = Z * vrow;
                float zc = fmaf(x, r0, fmaf(y, r1, (Z + tz) * r2));
                if (inl) {
                    aic += 1.0f;
                    zmx = fmaxf(zmx, zc);
                    zmn = fminf(zmn, zc);
                    szc += zc;
                }
            }
        }
        aic = wsum(aic); zmx = wmax(zmx); zmn = wmin(zmn); szc = wsum(szc);
        if (lane == 0) {
            s4[wid][0] = aic; s4[wid][1] = zmx; s4[wid][2] = zmn; s4[wid][3] = szc;
        }
        __syncthreads();
        if (tid == 0) {
            float t0 = 0, t1 = -INFINITY, t2 = INFINITY, t3 = 0;
            for (int w = 0; w < NWARP; w++) {
                t0 += s4[w][0]; t1 = fmaxf(t1, s4[w][1]);
                t2 = fminf(t2, s4[w][2]); t3 += s4[w][3];
            }
            float* pb = &g_partB[b * 4];
            pb[0] = t0; pb[1] = t1; pb[2] = t2; pb[3] = t3;
        }
    }

    // ===== B3: arrive-and-exit; LAST block finalizes =====
    __syncthreads();
    __threadfence();
    if (tid == 0) sh_last = (atomicAdd(&g_arrive, 1u) == NB - 1u) ? 1u : 0u;
    __syncthreads();
    if (!sh_last) return;

    __threadfence();
    {
        float ric = 0.0f, rzx = -INFINITY, rzn = INFINITY, rsz = 0.0f;
        float s0 = 0, s1 = 0, s2 = 0, s3 = 0, s4v = 0;
        if (tid < NB) {
            const float* pb = &g_partB[tid * 4];
            ric = pb[0]; rzx = pb[1]; rzn = pb[2]; rsz = pb[3];
            const float* pa = &g_partA[tid * 6];
            s0 = pa[0]; s1 = pa[1]; s2 = pa[2]; s3 = pa[3]; s4v = pa[4];
        }
        ric = blk_sum(ric, s30);
        rzx = blk_max(rzx, s30);
        rzn = blk_min(rzn, s30);
        rsz = blk_sum(rsz, s30);
        s0 = blk_sum(s0, s30); s1 = blk_sum(s1, s30); s2 = blk_sum(s2, s30);
        s3 = blk_sum(s3, s30); s4v = blk_sum(s4v, s30);
        if (tid == 0) {
            float cnt = fmaxf(s0, 1.0f);
            float lossX = sqrtf(s1 / cnt);
            float lossY = sqrtf(s2 / cnt);
            float lossZ = sqrtf(s3 / cnt);
            float RMSE_log = 10000.0f * sqrtf(s4v / cnt);
            float loss17 = RMSE_log * fabsf(10.0f * (3.0f - expf(lossX) - expf(lossY) - expf(lossZ)));

            float icnt = fmaxf(ric, 1.0f);
            float mean = rsz / icnt;
            float below = rzx - mean;
            float above = mean - rzn;
            if (above == 0.0f) above = 1e-7f;
            float pmdg = 1000.0f * (above + below);

            out[0] = RMSE_log;
            out[1] = lossX;
            out[2] = lossY;
            out[3] = lossZ;
            out[4] = pmdg;
            out[5] = loss17;
            out[6] = loss17 + pmdg;

            atomicExch(&g_arrive, 0u);   // reset for next graph replay
        }
    }
}

// ---------------- launcher ----------------
extern "C" void kernel_launch(void* const* d_in, const int* in_sizes, int n_in,
                              void* d_out, int out_size) {
    const float* fake = (const float*)d_in[0];
    const float* real = (const float*)d_in[1];
    const int* epoch = (const int*)d_in[2];
    float* out = (float*)d_out;
    (void)in_sizes; (void)n_in; (void)out_size;

    uint32_t ka, kb;
    threefry2x32(0u, 42u, 0u, 1u, ka, kb);

    k_all<<<NB, NT>>>(fake, real, epoch, out, ka, kb);
}

// round 16
// speedup vs baseline: 1.0337x; 1.0337x over previous
#include <cuda_runtime.h>
#include <math.h>
#include <stdint.h>

#define HH 360
#define WW 640
#define NP (HH*WW)          // 230400
#define NPLANES 1000
#define NPAIR   500
#define MINPTS 5000

#define CXc 334.081f
#define CYc 169.808f
#define FXc 460.585f
#define FYc 460.268f

#define NB 148
#define NT 960
#define NWARP 30
#define PX 10               // pixels per slot (divides 640)
#define PXF 8               // pixels counted on fma pipe (fcount)
#define SLOTS 160           // pixel slots per block
#define NACT 23040          // active slots total (NACT*PX = NP)
#define NGRP 6              // plane groups (5 warps each)
#define GRPW 5
#define GSZ 84              // pairs per group (last group: 500-5*84=80)
#define NF2 115200          // float2s per image
#define CHUNK2 779          // float2s per block in phase A

// ---------------- scratch ----------------
__device__ float    g_partA[NB * 6];     // cnt, dx2, dy2, dz2, dlog2, max
__device__ float    g_pp[8 * NPAIR];     // interleaved pair planes (scaled w)
__device__ int      g_counts[NPLANES];
__device__ float    g_partB[NB * 4];     // ic, zmax, zmin, sumzc
__device__ unsigned g_arrive;
__device__ volatile unsigned g_gen;

// ---------------- helpers ----------------
__host__ __device__ __forceinline__ uint32_t rotl32(uint32_t v, int s) { return (v << s) | (v >> (32 - s)); }

__host__ __device__ __forceinline__ void threefry2x32(uint32_t k0, uint32_t k1, uint32_t x0, uint32_t x1,
                                                      uint32_t& o0, uint32_t& o1) {
    uint32_t ks2 = k0 ^ k1 ^ 0x1BD11BDAu;
    x0 += k0; x1 += k1;
#define TFR(R) { x0 += x1; x1 = rotl32(x1, R); x1 ^= x0; }
    TFR(13) TFR(15) TFR(26) TFR(6)
    x0 += k1;  x1 += ks2 + 1u;
    TFR(17) TFR(29) TFR(16) TFR(24)
    x0 += ks2; x1 += k0 + 2u;
    TFR(13) TFR(15) TFR(26) TFR(6)
    x0 += k0;  x1 += k1 + 3u;
    TFR(17) TFR(29) TFR(16) TFR(24)
    x0 += k1;  x1 += ks2 + 4u;
    TFR(13) TFR(15) TFR(26) TFR(6)
    x0 += ks2; x1 += k0 + 5u;
#undef TFR
    o0 = x0; o1 = x1;
}

// packed f32x2
__device__ __forceinline__ unsigned long long pk2(float lo, float hi) {
    unsigned long long r;
    asm("mov.b64 %0, {%1, %2};" : "=l"(r) : "f"(lo), "f"(hi));
    return r;
}
__device__ __forceinline__ void upk2(unsigned long long v, float& lo, float& hi) {
    asm("mov.b64 {%0, %1}, %2;" : "=f"(lo), "=f"(hi) : "l"(v));
}
__device__ __forceinline__ unsigned long long ffma2(unsigned long long a, unsigned long long b, unsigned long long c) {
    unsigned long long r;
    asm("fma.rn.f32x2 %0, %1, %2, %3;" : "=l"(r) : "l"(a), "l"(b), "l"(c));
    return r;
}
// |x| <= th ? +1.0 : +0.0 accumulated (FSET + FADD, fma pipe, no predicates). NaN -> +0.
__device__ __forceinline__ void fcount(float& acc, float x, float th) {
    asm("{ .reg .f32 ta, ts;\n\t"
        "  abs.f32 ta, %1;\n\t"
        "  set.le.f32.f32 ts, ta, %2;\n\t"
        "  add.f32 %0, %0, ts; }"
        : "+f"(acc) : "f"(x), "f"(th));
}
// |x| <= th ? mask 0xFFFFFFFF : 0 accumulated (FSET-int + IADD, alu pipe).
// acc holds NEGATIVE count. NaN -> adds 0.
__device__ __forceinline__ void mcount(unsigned& acc, float x, float th) {
    asm("{ .reg .f32 ta; .reg .b32 m;\n\t"
        "  abs.f32 ta, %1;\n\t"
        "  set.le.u32.f32 m, ta, %2;\n\t"
        "  add.u32 %0, %0, m; }"
        : "+r"(acc) : "f"(x), "f"(th));
}

// UNNORMALIZED point (fake_pcd*1000, eps-filtered, nan->0)
__device__ __forceinline__ void pts_unnorm(const float* __restrict__ fake, int p,
                                           float& x, float& y, float& z) {
    float d = fake[p];
    bool valid = (d > 0.0f) && (d < 65535.0f);
    int r = p / WW, c = p - r * WW;
    float zz = d / 1000.0f;
    float px = zz * ((float)c - CXc) / FXc * 1000.0f;
    float py = zz * ((float)r - CYc) / FYc * 1000.0f;
    float pz = zz * 1000.0f;
    if (px == 0.0f) px = 1e-7f;
    if (py == 0.0f) py = 1e-7f;
    if (pz == 0.0f) pz = 1e-7f;
    if (!valid) { px = 0.0f; py = 0.0f; pz = 0.0f; }
    x = px; y = py; z = pz;
}

// ---------------- software grid barrier ----------------
__device__ __forceinline__ void gbar() {
    __syncthreads();
    __threadfence();
    if (threadIdx.x == 0) {
        unsigned g = g_gen;
        if (atomicAdd(&g_arrive, 1u) == NB - 1u) {
            atomicExch(&g_arrive, 0u);
            __threadfence();
            g_gen = g + 1u;
        } else {
            while (g_gen == g) { __nanosleep(64); }
        }
        __threadfence();
    }
    __syncthreads();
}

// warp-local reduce helpers (no sync)
__device__ __forceinline__ float wsum(float v) {
    for (int o = 16; o; o >>= 1) v += __shfl_down_sync(0xffffffffu, v, o);
    return v;
}
__device__ __forceinline__ float wmax(float v) {
    for (int o = 16; o; o >>= 1) v = fmaxf(v, __shfl_down_sync(0xffffffffu, v, o));
    return v;
}
__device__ __forceinline__ float wmin(float v) {
    for (int o = 16; o; o >>= 1) v = fminf(v, __shfl_down_sync(0xffffffffu, v, o));
    return v;
}

// classic block reductions (for once-per-kernel paths)
__device__ __forceinline__ float blk_sum(float v, float* s30) {
    __syncthreads();
    int lane = threadIdx.x & 31, w = threadIdx.x >> 5;
    v = wsum(v);
    if (lane == 0) s30[w] = v;
    __syncthreads();
    float r = 0.0f;
    if (threadIdx.x == 0) { for (int i = 0; i < NWARP; i++) r += s30[i]; }
    return r;
}
__device__ __forceinline__ float blk_max(float v, float* s30) {
    __syncthreads();
    int lane = threadIdx.x & 31, w = threadIdx.x >> 5;
    v = wmax(v);
    if (lane == 0) s30[w] = v;
    __syncthreads();
    float r = -INFINITY;
    if (threadIdx.x == 0) { for (int i = 0; i < NWARP; i++) r = fmaxf(r, s30[i]); }
    return r;
}
__device__ __forceinline__ float blk_min(float v, float* s30) {
    __syncthreads();
    int lane = threadIdx.x & 31, w = threadIdx.x >> 5;
    v = wmin(v);
    if (lane == 0) s30[w] = v;
    __syncthreads();
    float r = INFINITY;
    if (threadIdx.x == 0) { for (int i = 0; i < NWARP; i++) r = fminf(r, s30[i]); }
    return r;
}
__device__ __forceinline__ long long blk_maxll(long long v, long long* s30) {
    __syncthreads();
    int lane = threadIdx.x & 31, w = threadIdx.x >> 5;
    for (int o = 16; o; o >>= 1) {
        long long t = __shfl_down_sync(0xffffffffu, v, o);
        if (t > v) v = t;
    }
    if (lane == 0) s30[w] = v;
    __syncthreads();
    long long r = (-1LL) << 62;
    if (threadIdx.x == 0) { for (int i = 0; i < NWARP; i++) if (s30[i] > r) r = s30[i]; }
    return r;
}

// ---------------- the one kernel ----------------
__global__ void __launch_bounds__(NT) k_all(const float* __restrict__ fake,
                                            const float* __restrict__ real,
                                            const int* __restrict__ epoch_ptr,
                                            float* __restrict__ out,
                                            uint32_t ka, uint32_t kb) {
    __shared__ float     spp[8 * NPAIR];          // 16000 B
    __shared__ unsigned  swarp[NWARP * GSZ];      // 10080 B
    __shared__ float     s30[NWARP];
    __shared__ long long sll[NWARP];
    __shared__ float     s6[NWARP][6];
    __shared__ float     s4[NWARP][4];
    __shared__ float     sbc[16];
    __shared__ unsigned  sh_last;

    const int tid = threadIdx.x;
    const int b = blockIdx.x;
    const int lane = tid & 31, wid = tid >> 5;

    // ================= Phase A =================
    if (tid >= 32 && tid < 39) {
        int i = b * 7 + (tid - 32);
        if (i < NPLANES) g_counts[i] = 0;
    }

    // --- count point setup (UNNORMALIZED Z) ---
    const int slot = tid % SLOTS;
    const int grp = tid / SLOTS;
    const int gslot = b * SLOTS + slot;
    const bool act = gslot < NACT;
    const int p0 = act ? gslot * PX : 0;
    const int rowi = p0 / WW;
    const float vrow = ((float)rowi - CYc) / FYc;
    unsigned long long V = pk2(vrow, vrow);
    unsigned long long Up[PX], Zp[PX];
    {
        const float NaN = __int_as_float(0x7fffffff);
        int col0 = p0 - rowi * WW;
#pragma unroll
        for (int i = 0; i < PX; i++) {
            float d = __ldg(&fake[p0 + i]);
            bool val = (d > 0.0f) && (d < 65535.0f);
            float z = d / 1000.0f;
            float pz = z * 1000.0f;
            float Zi = val ? pz : 0.0f;
            if (!act) Zi = NaN;
            float ui = ((float)(col0 + i) - CXc) / FXc;
            Up[i] = pk2(ui, ui);
            Zp[i] = pk2(Zi, Zi);
        }
    }

    // --- plane generation ---
    if (tid < 7) {
        int pl = b * 7 + tid;
        if (pl < NPLANES) {
            float P[3][3];
#pragma unroll
            for (int j = 0; j < 3; j++) {
                uint32_t o0, o1;
                threefry2x32(ka, kb, 0u, (uint32_t)(pl * 3 + j), o0, o1);
                uint32_t idx = (o0 ^ o1) % (uint32_t)NP;
                pts_unnorm(fake, (int)idx, P[j][0], P[j][1], P[j][2]);
            }
            float ax = P[1][0] - P[0][0], ay = P[1][1] - P[0][1], az = P[1][2] - P[0][2];
            float bx = P[2][0] - P[0][0], by = P[2][1] - P[0][1], bz = P[2][2] - P[0][2];
            float nx = ay * bz - az * by;
            float ny = az * bx - ax * bz;
            float nz = ax * by - ay * bx;
            float nn = sqrtf(nx * nx + ny * ny + nz * nz);
            nx /= nn; ny /= nn; nz /= nn;
            float ws = -(nx * P[1][0] + ny * P[1][1] + nz * P[1][2]);
            int pr = pl >> 1, s = pl & 1;
            g_pp[8 * pr + 0 + s] = nx;
            g_pp[8 * pr + 2 + s] = ny;
            g_pp[8 * pr + 4 + s] = nz;
            g_pp[8 * pr + 6 + s] = ws;
        }
    }

    // --- pixel metrics (fused single-sync reduction) ---
    {
        float acnt = 0, adx = 0, ady = 0, adz = 0, adl = 0, amx = -INFINITY;
        int i = b * CHUNK2 + tid;
        if (tid < CHUNK2 && i < NF2) {
            float2 f2 = ((const float2*)fake)[i];
            float2 r2 = ((const float2*)real)[i];
#pragma unroll
            for (int j = 0; j < 2; j++) {
                int p = 2 * i + j;
                float fd = (&f2.x)[j], rd = (&r2.x)[j];
                int r = p / WW, c = p - r * WW;
                float cc = (float)c, rr = (float)r;
                bool vr = (rd > 0.0f) && (rd < 65535.0f);
                bool vf = (fd > 0.0f) && (fd < 65535.0f);

                float rz = rd / 1000.0f;
                float rX = rz * (cc - CXc) / FXc * 1000.0f;
                float rY = rz * (rr - CYc) / FYc * 1000.0f;
                float rZ = rz * 1000.0f;
                if (rX == 0.0f) rX = 1e-7f;
                if (rY == 0.0f) rY = 1e-7f;
                if (rZ == 0.0f) rZ = 1e-7f;

                float fz = fd / 1000.0f;
                float fX = fz * (cc - CXc) / FXc * 1000.0f;
                float fY = fz * (rr - CYc) / FYc * 1000.0f;
                float fZ = fz * 1000.0f;
                if (fX == 0.0f) fX = 1e-7f;
                if (fY == 0.0f) fY = 1e-7f;
                if (fZ == 0.0f) fZ = 1e-7f;

                bool m = vr && vf;
                if (m) {
                    float dx = rX - fX, dy = rY - fY, dz = rZ - fZ;
                    float dl = __logf(fabsf(rZ)) - __logf(fabsf(fZ));
                    acnt += 1.0f;
                    adx += dx * dx; ady += dy * dy; adz += dz * dz; adl += dl * dl;
                }
                if (vf) amx = fmaxf(amx, fmaxf(fmaxf(fX, fY), fZ));
            }
        }
        acnt = wsum(acnt); adx = wsum(adx); ady = wsum(ady);
        adz = wsum(adz); adl = wsum(adl); amx = wmax(amx);
        if (lane == 0) {
            s6[wid][0] = acnt; s6[wid][1] = adx; s6[wid][2] = ady;
            s6[wid][3] = adz; s6[wid][4] = adl; s6[wid][5] = amx;
        }
        __syncthreads();
        if (tid == 0) {
            float t0 = 0, t1 = 0, t2 = 0, t3 = 0, t4 = 0, t5 = -INFINITY;
            for (int w = 0; w < NWARP; w++) {
                t0 += s6[w][0]; t1 += s6[w][1]; t2 += s6[w][2];
                t3 += s6[w][3]; t4 += s6[w][4]; t5 = fmaxf(t5, s6[w][5]);
            }
            float* pa = &g_partA[b * 6];
            pa[0] = t0; pa[1] = t1; pa[2] = t2; pa[3] = t3; pa[4] = t4; pa[5] = t5;
        }
    }
    gbar();   // ===== B1 =====

    // --- per-block: maxv, th_s, rinv ---
    {
        float mx = -INFINITY;
        if (tid < NB) mx = g_partA[tid * 6 + 5];
        mx = blk_max(mx, s30);
        if (tid == 0) {
            int ep = epoch_ptr[0];
            float th = fmaxf((float)(0.025 - 0.001 * (double)ep), 0.005f);
            sbc[0] = mx;
            sbc[1] = th * mx;      // scaled threshold
            sbc[2] = 1.0f / mx;
        }
        __syncthreads();
    }
    const float th_s = sbc[1];

    // ================= Phase C: count (mixed fma/alu counting) =================
    {
        for (int i = tid; i < 2 * NPAIR; i += NT)
            ((float4*)spp)[i] = ((const float4*)g_pp)[i];
        __syncthreads();

        const int prBeg = grp * GSZ;
        const int prEnd = (grp == NGRP - 1) ? NPAIR : prBeg + GSZ;
        unsigned* myrow = swarp + wid * GSZ - prBeg;
        const float4* spp4 = (const float4*)spp;
#pragma unroll 2
        for (int pr = prBeg; pr < prEnd; pr++) {
            float4 q0 = spp4[2 * pr];      // a.lo a.hi b.lo b.hi
            float4 q1 = spp4[2 * pr + 1];  // c.lo c.hi w.lo w.hi (w scaled)
            unsigned long long A  = pk2(q0.x, q0.y);
            unsigned long long Bp = pk2(q0.z, q0.w);
            unsigned long long Cp = pk2(q1.x, q1.y);
            unsigned long long Wp = pk2(q1.z, q1.w);
            unsigned long long K = ffma2(V, Bp, Cp);
            float fclo = 0.0f, fchi = 0.0f;      // fma-pipe counters (px 0..7)
            unsigned mlo = 0u, mhi = 0u;         // alu-pipe negative counters (px 8..9)
#pragma unroll
            for (int i = 0; i < PX; i++) {
                unsigned long long e = ffma2(Up[i], A, K);
                unsigned long long dd = ffma2(Zp[i], e, Wp);
                float lo, hi;
                upk2(dd, lo, hi);
                if (i < PXF) {
                    fcount(fclo, lo, th_s);
                    fcount(fchi, hi, th_s);
                } else {
                    mcount(mlo, lo, th_s);
                    mcount(mhi, hi, th_s);
                }
            }
            float cpkf = fmaf(fchi, 65536.0f, fclo);         // exact, counts <= 8
            unsigned cpk = (unsigned)(int)cpkf
                         + (0u - mlo) + ((0u - mhi) << 16);  // add alu-side counts (<= 2 each)
            unsigned cs = __reduce_add_sync(0xffffffffu, cpk);
            if (lane == 0) myrow[pr] = cs;
        }
        __syncthreads();
        if (tid < NPAIR) {
            int pr = tid;
            int g = pr / GSZ;                  // 0..5
            int loc = pr - g * GSZ;
            unsigned s = 0;
#pragma unroll
            for (int w = 0; w < GRPW; w++) s += swarp[(g * GRPW + w) * GSZ + loc];
            atomicAdd(&g_counts[2 * pr],     (int)(s & 0xffffu));
            atomicAdd(&g_counts[2 * pr + 1], (int)(s >> 16));
        }
    }
    gbar();   // ===== B2 =====

    // ================= Phase D: argmax + zpass =================
    {
        long long bk = (-1LL) << 62;
        for (int t = tid; t < NPLANES; t += NT) {
            int cnt = g_counts[t];
            long long s = (cnt > MINPTS) ? (long long)cnt : -1LL;
            long long key = (s << 20) | (long long)(1023 - t);
            if (key > bk) bk = key;
        }
        bk = blk_maxll(bk, sll);
        if (tid == 0) {
            int best = 1023 - (int)(bk & 0xFFFFF);
            int pr = best >> 1, s = best & 1;
            float a  = spp[8 * pr + 0 + s];
            float bb = spp[8 * pr + 2 + s];
            float c  = spp[8 * pr + 4 + s];
            float ws = spp[8 * pr + 6 + s];
            float d = ws / sbc[0];            // normalized plane offset
            float tz = d / c;
            float n2 = a * a + bb * bb + c * c;
            float cos_t = c / sqrtf(n2);
            float sin_t = sqrtf((a * a + bb * bb) / n2);
            float sab = sqrtf(a * a + bb * bb);
            float u1 = bb / sab;
            float u2 = -a / sab;
            sbc[8]  = a; sbc[9] = bb; sbc[10] = c; sbc[11] = ws;
            sbc[12] = tz;
            sbc[13] = -u2 * sin_t;  // R[2][0]
            sbc[14] =  u1 * sin_t;  // R[2][1]
            sbc[15] =  cos_t;       // R[2][2]
        }
        __syncthreads();
        float a = sbc[8], bb = sbc[9], c = sbc[10], ws = sbc[11];
        float tz = sbc[12], r0 = sbc[13], r1 = sbc[14], r2 = sbc[15];
        float rinv = sbc[2];

        float aic = 0.0f, zmx = -INFINITY, zmn = INFINITY, szc = 0.0f;
        if (grp == 0) {
#pragma unroll
            for (int i = 0; i < PX; i++) {
                float u, Zu, dum;
                upk2(Up[i], u, dum);
                upk2(Zp[i], Zu, dum);
                float K = fmaf(vrow, bb, c);
                float e = fmaf(u, a, K);
                float dist = fmaf(Zu, e, ws);       // scaled dist
                bool inl = fabsf(dist) <= th_s;     // NaN -> false
                float Z = Zu * rinv;
                float x = Z * u, y = Z * vrow;
                float zc = fmaf(x, r0, fmaf(y, r1, (Z + tz) * r2));
                if (inl) {
                    aic += 1.0f;
                    zmx = fmaxf(zmx, zc);
                    zmn = fminf(zmn, zc);
                    szc += zc;
                }
            }
        }
        aic = wsum(aic); zmx = wmax(zmx); zmn = wmin(zmn); szc = wsum(szc);
        if (lane == 0) {
            s4[wid][0] = aic; s4[wid][1] = zmx; s4[wid][2] = zmn; s4[wid][3] = szc;
        }
        __syncthreads();
        if (tid == 0) {
            float t0 = 0, t1 = -INFINITY, t2 = INFINITY, t3 = 0;
            for (int w = 0; w < NWARP; w++) {
                t0 += s4[w][0]; t1 = fmaxf(t1, s4[w][1]);
                t2 = fminf(t2, s4[w][2]); t3 += s4[w][3];
            }
            float* pb = &g_partB[b * 4];
            pb[0] = t0; pb[1] = t1; pb[2] = t2; pb[3] = t3;
        }
    }

    // ===== B3: arrive-and-exit; LAST block finalizes =====
    __syncthreads();
    __threadfence();
    if (tid == 0) sh_last = (atomicAdd(&g_arrive, 1u) == NB - 1u) ? 1u : 0u;
    __syncthreads();
    if (!sh_last) return;

    __threadfence();
    {
        float ric = 0.0f, rzx = -INFINITY, rzn = INFINITY, rsz = 0.0f;
        float s0 = 0, s1 = 0, s2 = 0, s3 = 0, s4v = 0;
        if (tid < NB) {
            const float* pb = &g_partB[tid * 4];
            ric = pb[0]; rzx = pb[1]; rzn = pb[2]; rsz = pb[3];
            const float* pa = &g_partA[tid * 6];
            s0 = pa[0]; s1 = pa[1]; s2 = pa[2]; s3 = pa[3]; s4v = pa[4];
        }
        ric = blk_sum(ric, s30);
        rzx = blk_max(rzx, s30);
        rzn = blk_min(rzn, s30);
        rsz = blk_sum(rsz, s30);
        s0 = blk_sum(s0, s30); s1 = blk_sum(s1, s30); s2 = blk_sum(s2, s30);
        s3 = blk_sum(s3, s30); s4v = blk_sum(s4v, s30);
        if (tid == 0) {
            float cnt = fmaxf(s0, 1.0f);
            float lossX = sqrtf(s1 / cnt);
            float lossY = sqrtf(s2 / cnt);
            float lossZ = sqrtf(s3 / cnt);
            float RMSE_log = 10000.0f * sqrtf(s4v / cnt);
            float loss17 = RMSE_log * fabsf(10.0f * (3.0f - expf(lossX) - expf(lossY) - expf(lossZ)));

            float icnt = fmaxf(ric, 1.0f);
            float mean = rsz / icnt;
            float below = rzx - mean;
            float above = mean - rzn;
            if (above == 0.0f) above = 1e-7f;
            float pmdg = 1000.0f * (above + below);

            out[0] = RMSE_log;
            out[1] = lossX;
            out[2] = lossY;
            out[3] = lossZ;
            out[4] = pmdg;
            out[5] = loss17;
            out[6] = loss17 + pmdg;

            atomicExch(&g_arrive, 0u);   // reset for next graph replay
        }
    }
}

// ---------------- launcher ----------------
extern "C" void kernel_launch(void* const* d_in, const int* in_sizes, int n_in,
                              void* d_out, int out_size) {
    const float* fake = (const float*)d_in[0];
    const float* real = (const float*)d_in[1];
    const int* epoch = (const int*)d_in[2];
    float* out = (float*)d_out;
    (void)in_sizes; (void)n_in; (void)out_size;

    uint32_t ka, kb;
    threefry2x32(0u, 42u, 0u, 1u, ka, kb);

    k_all<<<NB, NT>>>(fake, real, epoch, out, ka, kb);
}

// round 17
// speedup vs baseline: 1.0708x; 1.0360x over previous
#include <cuda_runtime.h>
#include <math.h>
#include <stdint.h>

#define HH 360
#define WW 640
#define NP (HH*WW)          // 230400
#define NPLANES 1000
#define NPAIR   500
#define MINPTS 5000

#define CXc 334.081f
#define CYc 169.808f
#define FXc 460.585f
#define FYc 460.268f

#define NB 148
#define NT 960
#define NWARP 30
#define PX 10               // pixels per slot (divides 640)
#define PXF 8               // pixels counted on fma pipe (fcount)
#define SLOTS 160           // pixel slots per block
#define NACT 23040          // active slots total (NACT*PX = NP)
#define NGRP 6              // plane groups (5 warps each)
#define GRPW 5
#define GSZ 84              // pairs per group (last group: 500-5*84=80)
#define NF2 115200          // float2s per image
#define CHUNK2 779          // float2s per block in phase A

// ---------------- scratch ----------------
__device__ float    g_partA[NB * 6];     // cnt, dx2, dy2, dz2, dlog2, max
__device__ float    g_pp[8 * NPAIR];     // interleaved pair planes (scaled w)
__device__ int      g_counts[NPLANES];
__device__ float    g_partB[NB * 4];     // ic, zmax, zmin, sumzc
__device__ unsigned g_arrive;
__device__ volatile unsigned g_gen;

// ---------------- helpers ----------------
__host__ __device__ __forceinline__ uint32_t rotl32(uint32_t v, int s) { return (v << s) | (v >> (32 - s)); }

__host__ __device__ __forceinline__ void threefry2x32(uint32_t k0, uint32_t k1, uint32_t x0, uint32_t x1,
                                                      uint32_t& o0, uint32_t& o1) {
    uint32_t ks2 = k0 ^ k1 ^ 0x1BD11BDAu;
    x0 += k0; x1 += k1;
#define TFR(R) { x0 += x1; x1 = rotl32(x1, R); x1 ^= x0; }
    TFR(13) TFR(15) TFR(26) TFR(6)
    x0 += k1;  x1 += ks2 + 1u;
    TFR(17) TFR(29) TFR(16) TFR(24)
    x0 += ks2; x1 += k0 + 2u;
    TFR(13) TFR(15) TFR(26) TFR(6)
    x0 += k0;  x1 += k1 + 3u;
    TFR(17) TFR(29) TFR(16) TFR(24)
    x0 += k1;  x1 += ks2 + 4u;
    TFR(13) TFR(15) TFR(26) TFR(6)
    x0 += ks2; x1 += k0 + 5u;
#undef TFR
    o0 = x0; o1 = x1;
}

// packed f32x2
__device__ __forceinline__ unsigned long long pk2(float lo, float hi) {
    unsigned long long r;
    asm("mov.b64 %0, {%1, %2};" : "=l"(r) : "f"(lo), "f"(hi));
    return r;
}
__device__ __forceinline__ void upk2(unsigned long long v, float& lo, float& hi) {
    asm("mov.b64 {%0, %1}, %2;" : "=f"(lo), "=f"(hi) : "l"(v));
}
__device__ __forceinline__ unsigned long long ffma2(unsigned long long a, unsigned long long b, unsigned long long c) {
    unsigned long long r;
    asm("fma.rn.f32x2 %0, %1, %2, %3;" : "=l"(r) : "l"(a), "l"(b), "l"(c));
    return r;
}
// |x| <= th ? +1.0 : +0.0 accumulated (FSET + FADD, fma pipe, no predicates). NaN -> +0.
__device__ __forceinline__ void fcount(float& acc, float x, float th) {
    asm("{ .reg .f32 ta, ts;\n\t"
        "  abs.f32 ta, %1;\n\t"
        "  set.le.f32.f32 ts, ta, %2;\n\t"
        "  add.f32 %0, %0, ts; }"
        : "+f"(acc) : "f"(x), "f"(th));
}
// |x| <= th ? mask 0xFFFFFFFF : 0 accumulated (FSET-int + IADD, alu pipe).
// acc holds NEGATIVE count. NaN -> adds 0.
__device__ __forceinline__ void mcount(unsigned& acc, float x, float th) {
    asm("{ .reg .f32 ta; .reg .b32 m;\n\t"
        "  abs.f32 ta, %1;\n\t"
        "  set.le.u32.f32 m, ta, %2;\n\t"
        "  add.u32 %0, %0, m; }"
        : "+r"(acc) : "f"(x), "f"(th));
}

// UNNORMALIZED point (fake_pcd*1000, eps-filtered, nan->0)
__device__ __forceinline__ void pts_unnorm(const float* __restrict__ fake, int p,
                                           float& x, float& y, float& z) {
    float d = fake[p];
    bool valid = (d > 0.0f) && (d < 65535.0f);
    int r = p / WW, c = p - r * WW;
    float zz = d / 1000.0f;
    float px = zz * ((float)c - CXc) / FXc * 1000.0f;
    float py = zz * ((float)r - CYc) / FYc * 1000.0f;
    float pz = zz * 1000.0f;
    if (px == 0.0f) px = 1e-7f;
    if (py == 0.0f) py = 1e-7f;
    if (pz == 0.0f) pz = 1e-7f;
    if (!valid) { px = 0.0f; py = 0.0f; pz = 0.0f; }
    x = px; y = py; z = pz;
}

// ---------------- software grid barrier ----------------
__device__ __forceinline__ void gbar() {
    __syncthreads();
    __threadfence();
    if (threadIdx.x == 0) {
        unsigned g = g_gen;
        if (atomicAdd(&g_arrive, 1u) == NB - 1u) {
            atomicExch(&g_arrive, 0u);
            __threadfence();
            g_gen = g + 1u;
        } else {
            while (g_gen == g) { __nanosleep(64); }
        }
        __threadfence();
    }
    __syncthreads();
}

// warp-local reduce helpers (no sync)
__device__ __forceinline__ float wsum(float v) {
    for (int o = 16; o; o >>= 1) v += __shfl_down_sync(0xffffffffu, v, o);
    return v;
}
__device__ __forceinline__ float wmax(float v) {
    for (int o = 16; o; o >>= 1) v = fmaxf(v, __shfl_down_sync(0xffffffffu, v, o));
    return v;
}
__device__ __forceinline__ float wmin(float v) {
    for (int o = 16; o; o >>= 1) v = fminf(v, __shfl_down_sync(0xffffffffu, v, o));
    return v;
}

// classic block reductions (for once-per-kernel paths)
__device__ __forceinline__ float blk_sum(float v, float* s30) {
    __syncthreads();
    int lane = threadIdx.x & 31, w = threadIdx.x >> 5;
    v = wsum(v);
    if (lane == 0) s30[w] = v;
    __syncthreads();
    float r = 0.0f;
    if (threadIdx.x == 0) { for (int i = 0; i < NWARP; i++) r += s30[i]; }
    return r;
}
__device__ __forceinline__ float blk_max(float v, float* s30) {
    __syncthreads();
    int lane = threadIdx.x & 31, w = threadIdx.x >> 5;
    v = wmax(v);
    if (lane == 0) s30[w] = v;
    __syncthreads();
    float r = -INFINITY;
    if (threadIdx.x == 0) { for (int i = 0; i < NWARP; i++) r = fmaxf(r, s30[i]); }
    return r;
}
__device__ __forceinline__ float blk_min(float v, float* s30) {
    __syncthreads();
    int lane = threadIdx.x & 31, w = threadIdx.x >> 5;
    v = wmin(v);
    if (lane == 0) s30[w] = v;
    __syncthreads();
    float r = INFINITY;
    if (threadIdx.x == 0) { for (int i = 0; i < NWARP; i++) r = fminf(r, s30[i]); }
    return r;
}
__device__ __forceinline__ long long blk_maxll(long long v, long long* s30) {
    __syncthreads();
    int lane = threadIdx.x & 31, w = threadIdx.x >> 5;
    for (int o = 16; o; o >>= 1) {
        long long t = __shfl_down_sync(0xffffffffu, v, o);
        if (t > v) v = t;
    }
    if (lane == 0) s30[w] = v;
    __syncthreads();
    long long r = (-1LL) << 62;
    if (threadIdx.x == 0) { for (int i = 0; i < NWARP; i++) if (s30[i] > r) r = s30[i]; }
    return r;
}

// ---------------- the one kernel ----------------
__global__ void __launch_bounds__(NT) k_all(const float* __restrict__ fake,
                                            const float* __restrict__ real,
                                            const int* __restrict__ epoch_ptr,
                                            float* __restrict__ out,
                                            uint32_t ka, uint32_t kb) {
    __shared__ float     spp[8 * NPAIR];          // 16000 B
    __shared__ unsigned  swarp[NWARP * GSZ];      // 10080 B
    __shared__ float     s30[NWARP];
    __shared__ long long sll[NWARP];
    __shared__ float     s6[NWARP][6];
    __shared__ float     s4[NWARP][4];
    __shared__ float     sbc[16];
    __shared__ unsigned  sh_last;

    const int tid = threadIdx.x;
    const int b = blockIdx.x;
    const int lane = tid & 31, wid = tid >> 5;

    // ================= Phase A =================
    if (tid >= 32 && tid < 39) {
        int i = b * 7 + (tid - 32);
        if (i < NPLANES) g_counts[i] = 0;
    }

    // --- count point setup (UNNORMALIZED Z) ---
    const int slot = tid % SLOTS;
    const int grp = tid / SLOTS;
    const int gslot = b * SLOTS + slot;
    const bool act = gslot < NACT;
    const int p0 = act ? gslot * PX : 0;
    const int rowi = p0 / WW;
    const float vrow = ((float)rowi - CYc) / FYc;
    unsigned long long V = pk2(vrow, vrow);
    unsigned long long Up[PX], Zp[PX];
    {
        const float NaN = __int_as_float(0x7fffffff);
        int col0 = p0 - rowi * WW;
#pragma unroll
        for (int i = 0; i < PX; i++) {
            float d = __ldg(&fake[p0 + i]);
            bool val = (d > 0.0f) && (d < 65535.0f);
            float z = d / 1000.0f;
            float pz = z * 1000.0f;
            float Zi = val ? pz : 0.0f;
            if (!act) Zi = NaN;
            float ui = ((float)(col0 + i) - CXc) / FXc;
            Up[i] = pk2(ui, ui);
            Zp[i] = pk2(Zi, Zi);
        }
    }

    // --- plane generation ---
    if (tid < 7) {
        int pl = b * 7 + tid;
        if (pl < NPLANES) {
            float P[3][3];
#pragma unroll
            for (int j = 0; j < 3; j++) {
                uint32_t o0, o1;
                threefry2x32(ka, kb, 0u, (uint32_t)(pl * 3 + j), o0, o1);
                uint32_t idx = (o0 ^ o1) % (uint32_t)NP;
                pts_unnorm(fake, (int)idx, P[j][0], P[j][1], P[j][2]);
            }
            float ax = P[1][0] - P[0][0], ay = P[1][1] - P[0][1], az = P[1][2] - P[0][2];
            float bx = P[2][0] - P[0][0], by = P[2][1] - P[0][1], bz = P[2][2] - P[0][2];
            float nx = ay * bz - az * by;
            float ny = az * bx - ax * bz;
            float nz = ax * by - ay * bx;
            float nn = sqrtf(nx * nx + ny * ny + nz * nz);
            nx /= nn; ny /= nn; nz /= nn;
            float ws = -(nx * P[1][0] + ny * P[1][1] + nz * P[1][2]);
            int pr = pl >> 1, s = pl & 1;
            g_pp[8 * pr + 0 + s] = nx;
            g_pp[8 * pr + 2 + s] = ny;
            g_pp[8 * pr + 4 + s] = nz;
            g_pp[8 * pr + 6 + s] = ws;
        }
    }

    // --- pixel metrics (fused single-sync reduction) ---
    {
        float acnt = 0, adx = 0, ady = 0, adz = 0, adl = 0, amx = -INFINITY;
        int i = b * CHUNK2 + tid;
        if (tid < CHUNK2 && i < NF2) {
            float2 f2 = ((const float2*)fake)[i];
            float2 r2 = ((const float2*)real)[i];
#pragma unroll
            for (int j = 0; j < 2; j++) {
                int p = 2 * i + j;
                float fd = (&f2.x)[j], rd = (&r2.x)[j];
                int r = p / WW, c = p - r * WW;
                float cc = (float)c, rr = (float)r;
                bool vr = (rd > 0.0f) && (rd < 65535.0f);
                bool vf = (fd > 0.0f) && (fd < 65535.0f);

                float rz = rd / 1000.0f;
                float rX = rz * (cc - CXc) / FXc * 1000.0f;
                float rY = rz * (rr - CYc) / FYc * 1000.0f;
                float rZ = rz * 1000.0f;
                if (rX == 0.0f) rX = 1e-7f;
                if (rY == 0.0f) rY = 1e-7f;
                if (rZ == 0.0f) rZ = 1e-7f;

                float fz = fd / 1000.0f;
                float fX = fz * (cc - CXc) / FXc * 1000.0f;
                float fY = fz * (rr - CYc) / FYc * 1000.0f;
                float fZ = fz * 1000.0f;
                if (fX == 0.0f) fX = 1e-7f;
                if (fY == 0.0f) fY = 1e-7f;
                if (fZ == 0.0f) fZ = 1e-7f;

                bool m = vr && vf;
                if (m) {
                    float dx = rX - fX, dy = rY - fY, dz = rZ - fZ;
                    float dl = __logf(fabsf(rZ)) - __logf(fabsf(fZ));
                    acnt += 1.0f;
                    adx += dx * dx; ady += dy * dy; adz += dz * dz; adl += dl * dl;
                }
                if (vf) amx = fmaxf(amx, fmaxf(fmaxf(fX, fY), fZ));
            }
        }
        acnt = wsum(acnt); adx = wsum(adx); ady = wsum(ady);
        adz = wsum(adz); adl = wsum(adl); amx = wmax(amx);
        if (lane == 0) {
            s6[wid][0] = acnt; s6[wid][1] = adx; s6[wid][2] = ady;
            s6[wid][3] = adz; s6[wid][4] = adl; s6[wid][5] = amx;
        }
        __syncthreads();
        if (tid == 0) {
            float t0 = 0, t1 = 0, t2 = 0, t3 = 0, t4 = 0, t5 = -INFINITY;
            for (int w = 0; w < NWARP; w++) {
                t0 += s6[w][0]; t1 += s6[w][1]; t2 += s6[w][2];
                t3 += s6[w][3]; t4 += s6[w][4]; t5 = fmaxf(t5, s6[w][5]);
            }
            float* pa = &g_partA[b * 6];
            pa[0] = t0; pa[1] = t1; pa[2] = t2; pa[3] = t3; pa[4] = t4; pa[5] = t5;
        }
    }
    gbar();   // ===== B1 =====

    // --- per-block: maxv, th_s, rinv ---
    {
        float mx = -INFINITY;
        if (tid < NB) mx = g_partA[tid * 6 + 5];
        mx = blk_max(mx, s30);
        if (tid == 0) {
            int ep = epoch_ptr[0];
            float th = fmaxf((float)(0.025 - 0.001 * (double)ep), 0.005f);
            sbc[0] = mx;
            sbc[1] = th * mx;      // scaled threshold
            sbc[2] = 1.0f / mx;
        }
        __syncthreads();
    }
    const float th_s = sbc[1];

    // ===== Phase C: count (mixed fma/alu counting, parity-split fma chains) =====
    {
        for (int i = tid; i < 2 * NPAIR; i += NT)
            ((float4*)spp)[i] = ((const float4*)g_pp)[i];
        __syncthreads();

        const int prBeg = grp * GSZ;
        const int prEnd = (grp == NGRP - 1) ? NPAIR : prBeg + GSZ;
        unsigned* myrow = swarp + wid * GSZ - prBeg;
        const float4* spp4 = (const float4*)spp;
#pragma unroll 2
        for (int pr = prBeg; pr < prEnd; pr++) {
            float4 q0 = spp4[2 * pr];      // a.lo a.hi b.lo b.hi
            float4 q1 = spp4[2 * pr + 1];  // c.lo c.hi w.lo w.hi (w scaled)
            unsigned long long A  = pk2(q0.x, q0.y);
            unsigned long long Bp = pk2(q0.z, q0.w);
            unsigned long long Cp = pk2(q1.x, q1.y);
            unsigned long long Wp = pk2(q1.z, q1.w);
            unsigned long long K = ffma2(V, Bp, Cp);
            float fclo0 = 0.0f, fclo1 = 0.0f;    // parity-split fma counters (px 0..7)
            float fchi0 = 0.0f, fchi1 = 0.0f;
            unsigned mlo = 0u, mhi = 0u;         // alu-pipe negative counters (px 8..9)
#pragma unroll
            for (int i = 0; i < PX; i++) {
                unsigned long long e = ffma2(Up[i], A, K);
                unsigned long long dd = ffma2(Zp[i], e, Wp);
                float lo, hi;
                upk2(dd, lo, hi);
                if (i < PXF) {
                    if (i & 1) { fcount(fclo1, lo, th_s); fcount(fchi1, hi, th_s); }
                    else       { fcount(fclo0, lo, th_s); fcount(fchi0, hi, th_s); }
                } else {
                    mcount(mlo, lo, th_s);
                    mcount(mhi, hi, th_s);
                }
            }
            float fclo = fclo0 + fclo1;
            float fchi = fchi0 + fchi1;
            float cpkf = fmaf(fchi, 65536.0f, fclo);         // exact, counts <= 8
            unsigned cpk = (unsigned)(int)cpkf
                         + (0u - mlo) + ((0u - mhi) << 16);  // add alu-side counts (<= 2 each)
            unsigned cs = __reduce_add_sync(0xffffffffu, cpk);
            if (lane == 0) myrow[pr] = cs;
        }
        __syncthreads();
        if (tid < NPAIR) {
            int pr = tid;
            int g = pr / GSZ;                  // 0..5
            int loc = pr - g * GSZ;
            unsigned s = 0;
#pragma unroll
            for (int w = 0; w < GRPW; w++) s += swarp[(g * GRPW + w) * GSZ + loc];
            atomicAdd(&g_counts[2 * pr],     (int)(s & 0xffffu));
            atomicAdd(&g_counts[2 * pr + 1], (int)(s >> 16));
        }
    }
    gbar();   // ===== B2 =====

    // ================= Phase D: argmax + zpass =================
    {
        long long bk = (-1LL) << 62;
        for (int t = tid; t < NPLANES; t += NT) {
            int cnt = g_counts[t];
            long long s = (cnt > MINPTS) ? (long long)cnt : -1LL;
            long long key = (s << 20) | (long long)(1023 - t);
            if (key > bk) bk = key;
        }
        bk = blk_maxll(bk, sll);
        if (tid == 0) {
            int best = 1023 - (int)(bk & 0xFFFFF);
            int pr = best >> 1, s = best & 1;
            float a  = spp[8 * pr + 0 + s];
            float bb = spp[8 * pr + 2 + s];
            float c  = spp[8 * pr + 4 + s];
            float ws = spp[8 * pr + 6 + s];
            float d = ws / sbc[0];            // normalized plane offset
            float tz = d / c;
            float n2 = a * a + bb * bb + c * c;
            float cos_t = c / sqrtf(n2);
            float sin_t = sqrtf((a * a + bb * bb) / n2);
            float sab = sqrtf(a * a + bb * bb);
            float u1 = bb / sab;
            float u2 = -a / sab;
            sbc[8]  = a; sbc[9] = bb; sbc[10] = c; sbc[11] = ws;
            sbc[12] = tz;
            sbc[13] = -u2 * sin_t;  // R[2][0]
            sbc[14] =  u1 * sin_t;  // R[2][1]
            sbc[15] =  cos_t;       // R[2][2]
        }
        __syncthreads();
        float a = sbc[8], bb = sbc[9], c = sbc[10], ws = sbc[11];
        float tz = sbc[12], r0 = sbc[13], r1 = sbc[14], r2 = sbc[15];
        float rinv = sbc[2];

        float aic = 0.0f, zmx = -INFINITY, zmn = INFINITY, szc = 0.0f;
        if (grp == 0) {
#pragma unroll
            for (int i = 0; i < PX; i++) {
                float u, Zu, dum;
                upk2(Up[i], u, dum);
                upk2(Zp[i], Zu, dum);
                float K = fmaf(vrow, bb, c);
                float e = fmaf(u, a, K);
                float dist = fmaf(Zu, e, ws);       // scaled dist
                bool inl = fabsf(dist) <= th_s;     // NaN -> false
                float Z = Zu * rinv;
                float x = Z * u, y = Z * vrow;
                float zc = fmaf(x, r0, fmaf(y, r1, (Z + tz) * r2));
                if (inl) {
                    aic += 1.0f;
                    zmx = fmaxf(zmx, zc);
                    zmn = fminf(zmn, zc);
                    szc += zc;
                }
            }
        }
        aic = wsum(aic); zmx = wmax(zmx); zmn = wmin(zmn); szc = wsum(szc);
        if (lane == 0) {
            s4[wid][0] = aic; s4[wid][1] = zmx; s4[wid][2] = zmn; s4[wid][3] = szc;
        }
        __syncthreads();
        if (tid == 0) {
            float t0 = 0, t1 = -INFINITY, t2 = INFINITY, t3 = 0;
            for (int w = 0; w < NWARP; w++) {
                t0 += s4[w][0]; t1 = fmaxf(t1, s4[w][1]);
                t2 = fminf(t2, s4[w][2]); t3 += s4[w][3];
            }
            float* pb = &g_partB[b * 4];
            pb[0] = t0; pb[1] = t1; pb[2] = t2; pb[3] = t3;
        }
    }

    // ===== B3: arrive-and-exit; LAST block finalizes =====
    __syncthreads();
    __threadfence();
    if (tid == 0) sh_last = (atomicAdd(&g_arrive, 1u) == NB - 1u) ? 1u : 0u;
    __syncthreads();
    if (!sh_last) return;

    __threadfence();
    {
        float ric = 0.0f, rzx = -INFINITY, rzn = INFINITY, rsz = 0.0f;
        float s0 = 0, s1 = 0, s2 = 0, s3 = 0, s4v = 0;
        if (tid < NB) {
            const float* pb = &g_partB[tid * 4];
            ric = pb[0]; rzx = pb[1]; rzn = pb[2]; rsz = pb[3];
            const float* pa = &g_partA[tid * 6];
            s0 = pa[0]; s1 = pa[1]; s2 = pa[2]; s3 = pa[3]; s4v = pa[4];
        }
        ric = blk_sum(ric, s30);
        rzx = blk_max(rzx, s30);
        rzn = blk_min(rzn, s30);
        rsz = blk_sum(rsz, s30);
        s0 = blk_sum(s0, s30); s1 = blk_sum(s1, s30); s2 = blk_sum(s2, s30);
        s3 = blk_sum(s3, s30); s4v = blk_sum(s4v, s30);
        if (tid == 0) {
            float cnt = fmaxf(s0, 1.0f);
            float lossX = sqrtf(s1 / cnt);
            float lossY = sqrtf(s2 / cnt);
            float lossZ = sqrtf(s3 / cnt);
            float RMSE_log = 10000.0f * sqrtf(s4v / cnt);
            float loss17 = RMSE_log * fabsf(10.0f * (3.0f - expf(lossX) - expf(lossY) - expf(lossZ)));

            float icnt = fmaxf(ric, 1.0f);
            float mean = rsz / icnt;
            float below = rzx - mean;
            float above = mean - rzn;
            if (above == 0.0f) above = 1e-7f;
            float pmdg = 1000.0f * (above + below);

            out[0] = RMSE_log;
            out[1] = lossX;
            out[2] = lossY;
            out[3] = lossZ;
            out[4] = pmdg;
            out[5] = loss17;
            out[6] = loss17 + pmdg;

            atomicExch(&g_arrive, 0u);   // reset for next graph replay
        }
    }
}

// ---------------- launcher ----------------
extern "C" void kernel_launch(void* const* d_in, const int* in_sizes, int n_in,
                              void* d_out, int out_size) {
    const float* fake = (const float*)d_in[0];
    const float* real = (const float*)d_in[1];
    const int* epoch = (const int*)d_in[2];
    float* out = (float*)d_out;
    (void)in_sizes; (void)n_in; (void)out_size;

    uint32_t ka, kb;
    threefry2x32(0u, 42u, 0u, 1u, ka, kb);

    k_all<<<NB, NT>>>(fake, real, epoch, out, ka, kb);
}